// round 14
// baseline (speedup 1.0000x reference)
#include <cuda_runtime.h>
#include <cuda_bf16.h>
#include <math.h>
#include <string.h>
#include <stdint.h>

typedef unsigned int       u32;
typedef unsigned long long u64;

#define N_NODES   100000
#define N_EDGES   3200000
#define IN_CH     200
#define HID       64
#define N_GRAPHS  500
#define OUT_CH    2

#define SCAN_CHUNK 1024
#define NB ((N_NODES + SCAN_CHUNK - 1) / SCAN_CHUNK)   // 98

__device__ __forceinline__ u32 bf2_bits(__nv_bfloat162 v) {
    u32 u;
    memcpy(&u, &v, 4);
    return u;
}

__device__ __forceinline__ u32 tf32_hi_bits(float v) {
    u32 h;
    asm("cvt.rna.tf32.f32 %0, %1;" : "=r"(h) : "f"(v));
    return h;
}

// ---------------- scratch ----------------
__device__ u64   g_degcnt[N_NODES]; // {cnt<<40 | fx16 sum|w|}
__device__ float g_deg[N_NODES];    // dinv
__device__ int   g_cnt[N_NODES];
__device__ int   g_starts[N_NODES + 1];
__device__ int   g_bsum[128];
__device__ u32   g_rank[N_EDGES];   // edge rank within destination (from hist)
__device__ int2  g_edges[N_EDGES];  // {src, |w| bits}
__device__ float g_bufA[(size_t)N_NODES * HID];  // raw x@W1, later fp32 t
__device__ uint4 g_hbf [(size_t)N_NODES * 8];    // bf16 h' rows (128B/row)
__device__ uint4 g_hbf2[(size_t)N_NODES * 8];    // bf16 dinv*relu1 rows
__device__ float g_pooled[N_GRAPHS * HID];
__device__ int   g_cntg[N_GRAPHS];

// ---------------- init ----------------
__global__ void k_zero() {
    int i = blockIdx.x * blockDim.x + threadIdx.x;
    if (i < N_NODES) g_degcnt[i] = 0ULL;
    if (i < N_GRAPHS * HID) g_pooled[i] = 0.f;
    if (i < N_GRAPHS) g_cntg[i] = 0;
}

__global__ void k_cntg(const int* __restrict__ batch) {
    int i = blockIdx.x * blockDim.x + threadIdx.x;
    if (i < N_NODES) atomicAdd(&g_cntg[batch[i]], 1);
}

// ------ packed degree histogram (1 atomic / edge) + per-edge rank ---------
__global__ void k_hist(const int4* __restrict__ col4, const float4* __restrict__ wa4) {
    int i = blockIdx.x * blockDim.x + threadIdx.x;
    if (i >= N_EDGES / 4) return;
    int4   c = col4[i];
    float4 w = wa4[i];
    const u64 ONE = 1ULL << 40;
    u64 o0 = atomicAdd(&g_degcnt[c.x], ONE + (u64)(fabsf(w.x) * 65536.0f + 0.5f));
    u64 o1 = atomicAdd(&g_degcnt[c.y], ONE + (u64)(fabsf(w.y) * 65536.0f + 0.5f));
    u64 o2 = atomicAdd(&g_degcnt[c.z], ONE + (u64)(fabsf(w.z) * 65536.0f + 0.5f));
    u64 o3 = atomicAdd(&g_degcnt[c.w], ONE + (u64)(fabsf(w.w) * 65536.0f + 0.5f));
    uint4 r;
    r.x = (u32)(o0 >> 40);
    r.y = (u32)(o1 >> 40);
    r.z = (u32)(o2 >> 40);
    r.w = (u32)(o3 >> 40);
    *(uint4*)(g_rank + i * 4) = r;   // coalesced
}

__global__ void k_dinv() {
    int i = blockIdx.x * blockDim.x + threadIdx.x;
    if (i >= N_NODES) return;
    u64 v = g_degcnt[i];
    g_cnt[i] = (int)(v >> 40);
    float deg = (float)((double)(v & ((1ULL << 40) - 1)) * (1.0 / 65536.0));
    g_deg[i] = rsqrtf(deg + 1.0f);
}

// ---------------- exclusive scan ----------------
__global__ void k_scan1() {
    __shared__ int sh[SCAN_CHUNK];
    int idx = blockIdx.x * SCAN_CHUNK + threadIdx.x;
    sh[threadIdx.x] = (idx < N_NODES) ? g_cnt[idx] : 0;
    __syncthreads();
    for (int off = SCAN_CHUNK / 2; off > 0; off >>= 1) {
        if (threadIdx.x < off) sh[threadIdx.x] += sh[threadIdx.x + off];
        __syncthreads();
    }
    if (threadIdx.x == 0) g_bsum[blockIdx.x] = sh[0];
}

__global__ void k_scan2() {
    __shared__ int sh[128];
    int t = threadIdx.x;
    sh[t] = (t < NB) ? g_bsum[t] : 0;
    __syncthreads();
    if (t == 0) {
        int acc = 0;
        for (int b = 0; b < NB; b++) { int v = sh[b]; g_bsum[b] = acc; acc += v; }
        g_starts[N_NODES] = N_EDGES;
    }
}

__global__ void k_scan3() {
    __shared__ int sh[SCAN_CHUNK];
    int idx = blockIdx.x * SCAN_CHUNK + threadIdx.x;
    int v = (idx < N_NODES) ? g_cnt[idx] : 0;
    sh[threadIdx.x] = v;
    __syncthreads();
    for (int off = 1; off < SCAN_CHUNK; off <<= 1) {
        int t = (threadIdx.x >= off) ? sh[threadIdx.x - off] : 0;
        __syncthreads();
        sh[threadIdx.x] += t;
        __syncthreads();
    }
    if (idx < N_NODES) g_starts[idx] = g_bsum[blockIdx.x] + sh[threadIdx.x] - v;
}

// ---------------- CSR fill (atomic-free: starts[col] + rank) ---------------
__global__ void k_fill(const int4* __restrict__ row4, const int4* __restrict__ col4,
                       const float4* __restrict__ wa4) {
    int i = blockIdx.x * blockDim.x + threadIdx.x;
    if (i >= N_EDGES / 4) return;
    int4   r = row4[i];
    int4   c = col4[i];
    float4 w = wa4[i];
    uint4  k = *(const uint4*)(g_rank + i * 4);
    g_edges[g_starts[c.x] + k.x] = make_int2(r.x, __float_as_int(fabsf(w.x)));
    g_edges[g_starts[c.y] + k.y] = make_int2(r.y, __float_as_int(fabsf(w.y)));
    g_edges[g_starts[c.z] + k.z] = make_int2(r.z, __float_as_int(fabsf(w.z)));
    g_edges[g_starts[c.w] + k.w] = make_int2(r.w, __float_as_int(fabsf(w.w)));
}

// ============ warp-MMA GEMM1 (m16n8k16 bf16): bufA = x @ W1 (raw fp32) =====
#define SA 216                      // bf16 row stride (conflict-free frags)
#define MM_B_OFF (128 * SA * 2)     // 55296
#define MM_SMEM  (MM_B_OFF + 64 * SA * 2)  // 82944

__global__ void __launch_bounds__(256) k_gemm1_mma(const float* __restrict__ x,
                                                   const float* __restrict__ W1) {
    extern __shared__ __align__(16) char smem[];
    __nv_bfloat16* As = (__nv_bfloat16*)smem;               // [128][SA]
    __nv_bfloat16* Bs = (__nv_bfloat16*)(smem + MM_B_OFF);  // [64][SA] = W1^T
    int tid = threadIdx.x;
    int m0  = blockIdx.x * 128;

    for (int i = tid; i < 128 * 4; i += 256) {
        int r = i >> 2, c = 200 + ((i & 3) << 1);
        *(u32*)(As + r * SA + c) = 0;
    }
    for (int i = tid; i < 64 * 4; i += 256) {
        int r = i >> 2, c = 200 + ((i & 3) << 1);
        *(u32*)(Bs + r * SA + c) = 0;
    }
    for (int f = tid; f < 128 * 50; f += 256) {
        int r = f / 50, c4 = f % 50;
        int mg = m0 + r;
        float4 v = make_float4(0.f, 0.f, 0.f, 0.f);
        if (mg < N_NODES) v = *(const float4*)(x + (size_t)mg * IN_CH + c4 * 4);
        u32 p0 = bf2_bits(__float22bfloat162_rn(make_float2(v.x, v.y)));
        u32 p1 = bf2_bits(__float22bfloat162_rn(make_float2(v.z, v.w)));
        *(uint2*)(As + r * SA + c4 * 4) = make_uint2(p0, p1);
    }
    for (int idx = tid; idx < IN_CH * HID; idx += 256) {
        int k = idx / HID, n = idx % HID;
        Bs[n * SA + k] = __float2bfloat16(W1[idx]);
    }
    __syncthreads();

    int warp = tid >> 5, lane = tid & 31;
    int grp = lane >> 2, t4 = lane & 3;
    const __nv_bfloat16* Ar0 = As + (warp * 16 + grp) * SA;
    const __nv_bfloat16* Ar1 = Ar0 + 8 * SA;

    float c[8][4];
#pragma unroll
    for (int nt = 0; nt < 8; nt++)
#pragma unroll
        for (int j = 0; j < 4; j++) c[nt][j] = 0.f;

#pragma unroll
    for (int s = 0; s < 13; s++) {
        int k0 = s * 16;
        u32 a0 = *(const u32*)(Ar0 + k0 + 2 * t4);
        u32 a1 = *(const u32*)(Ar1 + k0 + 2 * t4);
        u32 a2 = *(const u32*)(Ar0 + k0 + 2 * t4 + 8);
        u32 a3 = *(const u32*)(Ar1 + k0 + 2 * t4 + 8);
#pragma unroll
        for (int nt = 0; nt < 8; nt++) {
            const __nv_bfloat16* Bp = Bs + (nt * 8 + grp) * SA + k0 + 2 * t4;
            u32 b0 = *(const u32*)(Bp);
            u32 b1 = *(const u32*)(Bp + 8);
            asm volatile(
                "mma.sync.aligned.m16n8k16.row.col.f32.bf16.bf16.f32 "
                "{%0,%1,%2,%3}, {%4,%5,%6,%7}, {%8,%9}, {%0,%1,%2,%3};"
                : "+f"(c[nt][0]), "+f"(c[nt][1]), "+f"(c[nt][2]), "+f"(c[nt][3])
                : "r"(a0), "r"(a1), "r"(a2), "r"(a3), "r"(b0), "r"(b1));
        }
    }

    int mA = m0 + warp * 16 + grp;
    int mB = mA + 8;
#pragma unroll
    for (int nt = 0; nt < 8; nt++) {
        int col = nt * 8 + 2 * t4;
        if (mA < N_NODES)
            *(float2*)(g_bufA + (size_t)mA * 64 + col) = make_float2(c[nt][0], c[nt][1]);
        if (mB < N_NODES)
            *(float2*)(g_bufA + (size_t)mB * 64 + col) = make_float2(c[nt][2], c[nt][3]);
    }
}

// == 3xTF32 warp-MMA GEMM2 + pooling: pooled[batch[m]] += relu(t@W2+b2) =====
#define SB2 68                              // fp32 row stride; 68 % 32 == 4
#define P2_BH_OFF (128 * SB2 * 4)           // 34816
#define P2_BL_OFF (P2_BH_OFF + 64 * SB2 * 4)// 52224
#define P2_SMEM   (P2_BL_OFF + 64 * SB2 * 4)// 69632 (C overlays A tile)

__global__ void __launch_bounds__(256) k_gemm2pool_tf32(const float* __restrict__ W2,
                                                        const float* __restrict__ b2,
                                                        const int* __restrict__ batch) {
    extern __shared__ __align__(16) char smem[];
    float* As = (float*)smem;                 // [128][SB2] = t tile (fp32)
    u32*   Bh = (u32*)(smem + P2_BH_OFF);     // [64][SB2]  = tf32(W2^T)
    u32*   Bl = (u32*)(smem + P2_BL_OFF);     // [64][SB2]  = tf32(residual)
    int tid = threadIdx.x;
    int m0  = blockIdx.x * 128;

    for (int f = tid; f < 128 * 16; f += 256) {
        int r = f >> 4, q = f & 15;
        int mg = m0 + r;
        float4 v = make_float4(0.f, 0.f, 0.f, 0.f);
        if (mg < N_NODES) v = *(const float4*)(g_bufA + (size_t)mg * 64 + q * 4);
        *(float4*)(As + r * SB2 + q * 4) = v;
    }
    for (int idx = tid; idx < HID * HID; idx += 256) {
        int k = idx / HID, n = idx % HID;
        float w = W2[idx];
        u32 hb = tf32_hi_bits(w);
        float lo = w - __uint_as_float(hb);
        Bh[n * SB2 + k] = hb;
        Bl[n * SB2 + k] = tf32_hi_bits(lo);
    }
    __syncthreads();

    int warp = tid >> 5, lane = tid & 31;
    int grp = lane >> 2, t4 = lane & 3;
    int rA = warp * 16 + grp;
    const float* Ar0 = As + rA * SB2;
    const float* Ar1 = Ar0 + 8 * SB2;

    float c[8][4];
#pragma unroll
    for (int nt = 0; nt < 8; nt++)
#pragma unroll
        for (int j = 0; j < 4; j++) c[nt][j] = 0.f;

#pragma unroll
    for (int s = 0; s < 8; s++) {
        int k0 = s * 8;
        float av0 = Ar0[k0 + t4];
        float av1 = Ar1[k0 + t4];
        float av2 = Ar0[k0 + t4 + 4];
        float av3 = Ar1[k0 + t4 + 4];
        u32 ah0 = tf32_hi_bits(av0), ah1 = tf32_hi_bits(av1);
        u32 ah2 = tf32_hi_bits(av2), ah3 = tf32_hi_bits(av3);
        u32 al0 = tf32_hi_bits(av0 - __uint_as_float(ah0));
        u32 al1 = tf32_hi_bits(av1 - __uint_as_float(ah1));
        u32 al2 = tf32_hi_bits(av2 - __uint_as_float(ah2));
        u32 al3 = tf32_hi_bits(av3 - __uint_as_float(ah3));
#pragma unroll
        for (int nt = 0; nt < 8; nt++) {
            int boff = (nt * 8 + grp) * SB2 + k0;
            u32 bh0 = Bh[boff + t4], bh1 = Bh[boff + t4 + 4];
            u32 bl0 = Bl[boff + t4], bl1 = Bl[boff + t4 + 4];
            asm volatile(
                "mma.sync.aligned.m16n8k8.row.col.f32.tf32.tf32.f32 "
                "{%0,%1,%2,%3}, {%4,%5,%6,%7}, {%8,%9}, {%0,%1,%2,%3};"
                : "+f"(c[nt][0]), "+f"(c[nt][1]), "+f"(c[nt][2]), "+f"(c[nt][3])
                : "r"(ah0), "r"(ah1), "r"(ah2), "r"(ah3), "r"(bl0), "r"(bl1));
            asm volatile(
                "mma.sync.aligned.m16n8k8.row.col.f32.tf32.tf32.f32 "
                "{%0,%1,%2,%3}, {%4,%5,%6,%7}, {%8,%9}, {%0,%1,%2,%3};"
                : "+f"(c[nt][0]), "+f"(c[nt][1]), "+f"(c[nt][2]), "+f"(c[nt][3])
                : "r"(al0), "r"(al1), "r"(al2), "r"(al3), "r"(bh0), "r"(bh1));
            asm volatile(
                "mma.sync.aligned.m16n8k8.row.col.f32.tf32.tf32.f32 "
                "{%0,%1,%2,%3}, {%4,%5,%6,%7}, {%8,%9}, {%0,%1,%2,%3};"
                : "+f"(c[nt][0]), "+f"(c[nt][1]), "+f"(c[nt][2]), "+f"(c[nt][3])
                : "r"(ah0), "r"(ah1), "r"(ah2), "r"(ah3), "r"(bh0), "r"(bh1));
        }
    }
    __syncthreads();

    float* Cs = (float*)smem;
#pragma unroll
    for (int nt = 0; nt < 8; nt++) {
        int col = nt * 8 + 2 * t4;
        *(float2*)(Cs + rA * SB2 + col)       = make_float2(c[nt][0], c[nt][1]);
        *(float2*)(Cs + (rA + 8) * SB2 + col) = make_float2(c[nt][2], c[nt][3]);
    }
    __syncthreads();

    int r0 = (tid >> 4) * 8;
    int c0 = (tid & 15) * 4;
    float4 bv = *(const float4*)(b2 + c0);
#pragma unroll
    for (int i = 0; i < 8; i++) {
        int m = m0 + r0 + i;
        if (m < N_NODES) {
            float4 v = *(float4*)(Cs + (r0 + i) * SB2 + c0);
            v.x = fmaxf(v.x + bv.x, 0.f);
            v.y = fmaxf(v.y + bv.y, 0.f);
            v.z = fmaxf(v.z + bv.z, 0.f);
            v.w = fmaxf(v.w + bv.w, 0.f);
            int g = batch[m];
            float* dst = g_pooled + g * 64 + c0;
#if __CUDA_ARCH__ >= 900
            atomicAdd((float4*)dst, v);
#else
            atomicAdd(dst + 0, v.x);
            atomicAdd(dst + 1, v.y);
            atomicAdd(dst + 2, v.z);
            atomicAdd(dst + 3, v.w);
#endif
        }
    }
}

// ---------------- convert bufA -> bf16 with dinv scale ----------------
__global__ void k_conv() {
    int i = blockIdx.x * blockDim.x + threadIdx.x;   // one uint4 (8 feats) / thread
    if (i >= N_NODES * 8) return;
    int n = i >> 3;
    float d = g_deg[n];
    const float* src = g_bufA + (size_t)i * 8;
    float4 v0 = *(const float4*)(src);
    float4 v1 = *(const float4*)(src + 4);
    uint4 o;
    o.x = bf2_bits(__float22bfloat162_rn(make_float2(v0.x * d, v0.y * d)));
    o.y = bf2_bits(__float22bfloat162_rn(make_float2(v0.z * d, v0.w * d)));
    o.z = bf2_bits(__float22bfloat162_rn(make_float2(v1.x * d, v1.y * d)));
    o.w = bf2_bits(__float22bfloat162_rn(make_float2(v1.z * d, v1.w * d)));
    g_hbf[i] = o;
}

// ---- 4-edges-per-warp gather: 8 lanes/edge, 0.5 LDG per edge --------------
__device__ __forceinline__ void gather_core(const uint4* __restrict__ h,
                                            int s, int e, int eg, int fl,
                                            float acc[8]) {
#pragma unroll 2
    for (int i = s; i < e; i += 4) {
        int idx = i + eg;
        int cl  = idx < e ? idx : (e - 1);
        int2 ed = g_edges[cl];
        float w = idx < e ? __int_as_float(ed.y) : 0.f;
        uint4 hv = h[(size_t)ed.x * 8 + fl];
        float2 p0 = __bfloat1622float2(*(__nv_bfloat162*)&hv.x);
        float2 p1 = __bfloat1622float2(*(__nv_bfloat162*)&hv.y);
        float2 p2 = __bfloat1622float2(*(__nv_bfloat162*)&hv.z);
        float2 p3 = __bfloat1622float2(*(__nv_bfloat162*)&hv.w);
        acc[0] = fmaf(w, p0.x, acc[0]);
        acc[1] = fmaf(w, p0.y, acc[1]);
        acc[2] = fmaf(w, p1.x, acc[2]);
        acc[3] = fmaf(w, p1.y, acc[3]);
        acc[4] = fmaf(w, p2.x, acc[4]);
        acc[5] = fmaf(w, p2.y, acc[5]);
        acc[6] = fmaf(w, p3.x, acc[6]);
        acc[7] = fmaf(w, p3.y, acc[7]);
    }
#pragma unroll
    for (int k = 0; k < 8; k++) {
        acc[k] += __shfl_xor_sync(0xffffffffu, acc[k], 8);
        acc[k] += __shfl_xor_sync(0xffffffffu, acc[k], 16);
    }
}

// layer 1: g_hbf2[n] = bf16( dinv * relu( dinv*(sum + hn) + b1 ) )
__global__ void __launch_bounds__(256) k_gather1(const float* __restrict__ bias) {
    int wid  = (blockIdx.x * blockDim.x + threadIdx.x) >> 5;
    int lane = threadIdx.x & 31;
    if (wid >= N_NODES) return;
    int s = g_starts[wid];
    int e = g_starts[wid + 1];
    int eg = lane >> 3;
    int fl = lane & 7;
    float acc[8] = {0.f, 0.f, 0.f, 0.f, 0.f, 0.f, 0.f, 0.f};
    gather_core(g_hbf, s, e, eg, fl, acc);
    if (eg == 0) {
        uint4 hn = g_hbf[(size_t)wid * 8 + fl];
        float2 q0 = __bfloat1622float2(*(__nv_bfloat162*)&hn.x);
        float2 q1 = __bfloat1622float2(*(__nv_bfloat162*)&hn.y);
        float2 q2 = __bfloat1622float2(*(__nv_bfloat162*)&hn.z);
        float2 q3 = __bfloat1622float2(*(__nv_bfloat162*)&hn.w);
        float d = g_deg[wid];
        float4 bA = *(const float4*)(bias + fl * 8);
        float4 bB = *(const float4*)(bias + fl * 8 + 4);
        float o0 = fmaxf(fmaf(d, acc[0] + q0.x, bA.x), 0.f) * d;
        float o1 = fmaxf(fmaf(d, acc[1] + q0.y, bA.y), 0.f) * d;
        float o2 = fmaxf(fmaf(d, acc[2] + q1.x, bA.z), 0.f) * d;
        float o3 = fmaxf(fmaf(d, acc[3] + q1.y, bA.w), 0.f) * d;
        float o4 = fmaxf(fmaf(d, acc[4] + q2.x, bB.x), 0.f) * d;
        float o5 = fmaxf(fmaf(d, acc[5] + q2.y, bB.y), 0.f) * d;
        float o6 = fmaxf(fmaf(d, acc[6] + q3.x, bB.z), 0.f) * d;
        float o7 = fmaxf(fmaf(d, acc[7] + q3.y, bB.w), 0.f) * d;
        uint4 o;
        o.x = bf2_bits(__float22bfloat162_rn(make_float2(o0, o1)));
        o.y = bf2_bits(__float22bfloat162_rn(make_float2(o2, o3)));
        o.z = bf2_bits(__float22bfloat162_rn(make_float2(o4, o5)));
        o.w = bf2_bits(__float22bfloat162_rn(make_float2(o6, o7)));
        g_hbf2[(size_t)wid * 8 + fl] = o;
    }
}

// layer 2 aggregation: g_bufA[n,:] = dinv*(sum + hn)   (fp32 t)
__global__ void __launch_bounds__(256) k_gather2() {
    int wid  = (blockIdx.x * blockDim.x + threadIdx.x) >> 5;
    int lane = threadIdx.x & 31;
    if (wid >= N_NODES) return;
    int s = g_starts[wid];
    int e = g_starts[wid + 1];
    int eg = lane >> 3;
    int fl = lane & 7;
    float acc[8] = {0.f, 0.f, 0.f, 0.f, 0.f, 0.f, 0.f, 0.f};
    gather_core(g_hbf2, s, e, eg, fl, acc);
    if (eg == 0) {
        uint4 hn = g_hbf2[(size_t)wid * 8 + fl];
        float2 q0 = __bfloat1622float2(*(__nv_bfloat162*)&hn.x);
        float2 q1 = __bfloat1622float2(*(__nv_bfloat162*)&hn.y);
        float2 q2 = __bfloat1622float2(*(__nv_bfloat162*)&hn.z);
        float2 q3 = __bfloat1622float2(*(__nv_bfloat162*)&hn.w);
        float d = g_deg[wid];
        float* dst = g_bufA + (size_t)wid * 64 + fl * 8;
        float4 oA, oB;
        oA.x = d * (acc[0] + q0.x);
        oA.y = d * (acc[1] + q0.y);
        oA.z = d * (acc[2] + q1.x);
        oA.w = d * (acc[3] + q1.y);
        oB.x = d * (acc[4] + q2.x);
        oB.y = d * (acc[5] + q2.y);
        oB.z = d * (acc[6] + q3.x);
        oB.w = d * (acc[7] + q3.y);
        *(float4*)(dst)     = oA;
        *(float4*)(dst + 4) = oB;
    }
}

// ---------------- final MLP ----------------
__global__ void __launch_bounds__(256) k_mlp(const float* __restrict__ L1,
                                             const float* __restrict__ c1,
                                             const float* __restrict__ L2,
                                             const float* __restrict__ c2,
                                             float* __restrict__ out) {
    int g = blockIdx.x;
    __shared__ float pm[HID];
    __shared__ float fea[IN_CH];
    __shared__ float red[256];
    int tid = threadIdx.x;
    if (tid < HID) {
        float cv = (float)g_cntg[g];
        pm[tid] = g_pooled[g * HID + tid] / fmaxf(cv, 1.0f);
    }
    __syncthreads();
    if (tid < IN_CH) {
        float s = c1[tid];
#pragma unroll
        for (int k = 0; k < HID; k++) s = fmaf(pm[k], L1[k * IN_CH + tid], s);
        fea[tid] = fmaxf(s, 0.f);
    }
    __syncthreads();
    float p0 = 0.f, p1 = 0.f;
    if (tid < IN_CH) {
        float fv = fea[tid];
        p0 = fv * L2[tid * OUT_CH];
        p1 = fv * L2[tid * OUT_CH + 1];
    }
    red[tid] = p0; __syncthreads();
    for (int off = 128; off > 0; off >>= 1) {
        if (tid < off) red[tid] += red[tid + off];
        __syncthreads();
    }
    float s0 = red[0];
    __syncthreads();
    red[tid] = p1; __syncthreads();
    for (int off = 128; off > 0; off >>= 1) {
        if (tid < off) red[tid] += red[tid + off];
        __syncthreads();
    }
    if (tid == 0) {
        out[g * OUT_CH]     = s0     + c2[0];
        out[g * OUT_CH + 1] = red[0] + c2[1];
    }
}

// ---------------- launch ----------------
extern "C" void kernel_launch(void* const* d_in, const int* in_sizes, int n_in,
                              void* d_out, int out_size) {
    const float* x         = (const float*)d_in[0];
    const int*   edge_idx  = (const int*)d_in[1];
    const float* edge_attr = (const float*)d_in[2];
    const int*   batch     = (const int*)d_in[3];
    const float* W1        = (const float*)d_in[4];
    const float* b1        = (const float*)d_in[5];
    const float* W2        = (const float*)d_in[6];
    const float* b2        = (const float*)d_in[7];
    const float* L1        = (const float*)d_in[8];
    const float* c1        = (const float*)d_in[9];
    const float* L2        = (const float*)d_in[10];
    const float* c2        = (const float*)d_in[11];
    float* out = (float*)d_out;

    const int* row = edge_idx;
    const int* col = edge_idx + N_EDGES;

    static cudaStream_t s2 = nullptr;
    static cudaEvent_t  evF = nullptr, evD = nullptr, evJ = nullptr;
    if (s2 == nullptr) {
        cudaStreamCreateWithFlags(&s2, cudaStreamNonBlocking);
        cudaEventCreateWithFlags(&evF, cudaEventDisableTiming);
        cudaEventCreateWithFlags(&evD, cudaEventDisableTiming);
        cudaEventCreateWithFlags(&evJ, cudaEventDisableTiming);
        cudaFuncSetAttribute(k_gemm1_mma, cudaFuncAttributeMaxDynamicSharedMemorySize,
                             MM_SMEM);
        cudaFuncSetAttribute(k_gemm2pool_tf32, cudaFuncAttributeMaxDynamicSharedMemorySize,
                             P2_SMEM);
    }

    const int TB = 256;
    int nodeBlocks   = (N_NODES + TB - 1) / TB;
    int edge4Blocks  = (N_EDGES / 4 + TB - 1) / TB;
    int gemmBlocks   = (N_NODES + 127) / 128;
    int gatherBlocks = (N_NODES * 32 + TB - 1) / TB;
    int convBlocks   = (N_NODES * 8 + TB - 1) / TB;

    // fork: MMA GEMM1 (raw) has no dependencies, starts at t=0
    cudaEventRecord(evF, 0);
    cudaStreamWaitEvent(s2, evF, 0);
    k_gemm1_mma<<<gemmBlocks, 256, MM_SMEM, s2>>>(x, W1);  // bufA = x @ W1 (raw)

    k_zero<<<nodeBlocks, TB>>>();
    k_cntg<<<nodeBlocks, TB>>>(batch);
    k_hist<<<edge4Blocks, TB>>>((const int4*)col, (const float4*)edge_attr);
    k_dinv<<<nodeBlocks, TB>>>();
    cudaEventRecord(evD, 0);                          // dinv ready

    cudaStreamWaitEvent(s2, evD, 0);
    k_conv<<<convBlocks, TB, 0, s2>>>();              // g_hbf = bf16(dinv*bufA)
    cudaEventRecord(evJ, s2);

    k_scan1<<<NB, SCAN_CHUNK>>>();
    k_scan2<<<1, 128>>>();
    k_scan3<<<NB, SCAN_CHUNK>>>();
    k_fill<<<edge4Blocks, TB>>>((const int4*)row, (const int4*)col,
                                (const float4*)edge_attr);

    cudaStreamWaitEvent(0, evJ, 0);                   // join

    k_gather1<<<gatherBlocks, TB>>>(b1);              // g_hbf2 = dinv*relu1 (bf16)
    k_gather2<<<gatherBlocks, TB>>>();                // g_bufA = t (fp32)
    k_gemm2pool_tf32<<<gemmBlocks, 256, P2_SMEM>>>(W2, b2, batch);
    k_mlp<<<N_GRAPHS, 256>>>(L1, c1, L2, c2, out);
}

// round 15
// speedup vs baseline: 1.0740x; 1.0740x over previous
#include <cuda_runtime.h>
#include <cuda_bf16.h>
#include <math.h>
#include <string.h>
#include <stdint.h>

typedef unsigned int       u32;
typedef unsigned long long u64;

#define N_NODES   100000
#define N_EDGES   3200000
#define IN_CH     200
#define HID       64
#define N_GRAPHS  500
#define OUT_CH    2

#define SCAN_CHUNK 1024
#define NB ((N_NODES + SCAN_CHUNK - 1) / SCAN_CHUNK)   // 98

__device__ __forceinline__ u32 bf2_bits(__nv_bfloat162 v) {
    u32 u;
    memcpy(&u, &v, 4);
    return u;
}

__device__ __forceinline__ u32 tf32_hi_bits(float v) {
    u32 h;
    asm("cvt.rna.tf32.f32 %0, %1;" : "=r"(h) : "f"(v));
    return h;
}

// ---------------- scratch ----------------
__device__ u64   g_degcnt[N_NODES]; // {cnt<<40 | fx16 sum|w|}
__device__ float g_deg[N_NODES];    // dinv
__device__ int   g_cnt[N_NODES];
__device__ int   g_cursor[N_NODES];
__device__ int   g_starts[N_NODES + 1];
__device__ int   g_bsum[128];
__device__ int2  g_edges[N_EDGES];  // {src, |w| bits}
__device__ float g_bufA[(size_t)N_NODES * HID];  // raw x@W1, later fp32 t
__device__ uint4 g_hbf [(size_t)N_NODES * 8];    // bf16 h' rows (128B/row)
__device__ uint4 g_hbf2[(size_t)N_NODES * 8];    // bf16 dinv*relu1 rows
__device__ float g_pooled[N_GRAPHS * HID];

// ---------------- init (zero degcnt + pooled; set sentinel) ----------------
__global__ void k_init() {
    int i = blockIdx.x * blockDim.x + threadIdx.x;
    if (i < N_NODES) g_degcnt[i] = 0ULL;
    if (i < N_GRAPHS * HID) g_pooled[i] = 0.f;
    if (i == 0) g_starts[N_NODES] = N_EDGES;
}

// ---------------- packed degree histogram (1 non-returning atomic/edge) ----
__global__ void k_hist(const int4* __restrict__ col4, const float4* __restrict__ wa4) {
    int i = blockIdx.x * blockDim.x + threadIdx.x;
    if (i >= N_EDGES / 4) return;
    int4   c = col4[i];
    float4 w = wa4[i];
    const u64 ONE = 1ULL << 40;
    atomicAdd(&g_degcnt[c.x], ONE + (u64)(fabsf(w.x) * 65536.0f + 0.5f));
    atomicAdd(&g_degcnt[c.y], ONE + (u64)(fabsf(w.y) * 65536.0f + 0.5f));
    atomicAdd(&g_degcnt[c.z], ONE + (u64)(fabsf(w.z) * 65536.0f + 0.5f));
    atomicAdd(&g_degcnt[c.w], ONE + (u64)(fabsf(w.w) * 65536.0f + 0.5f));
}

// ---------------- scan1: unpack degcnt -> dinv + cnt, per-block sums -------
__global__ void k_scan1() {
    __shared__ int sh[SCAN_CHUNK];
    int idx = blockIdx.x * SCAN_CHUNK + threadIdx.x;
    int v = 0;
    if (idx < N_NODES) {
        u64 dc = g_degcnt[idx];
        v = (int)(dc >> 40);
        float deg = (float)((double)(dc & ((1ULL << 40) - 1)) * (1.0 / 65536.0));
        g_deg[idx] = rsqrtf(deg + 1.0f);
        g_cnt[idx] = v;
    }
    sh[threadIdx.x] = v;
    __syncthreads();
    for (int off = SCAN_CHUNK / 2; off > 0; off >>= 1) {
        if (threadIdx.x < off) sh[threadIdx.x] += sh[threadIdx.x + off];
        __syncthreads();
    }
    if (threadIdx.x == 0) g_bsum[blockIdx.x] = sh[0];
}

// ------- scan3: local Hillis-Steele + in-block prefix of block sums --------
__global__ void k_scan3() {
    __shared__ int sh[SCAN_CHUNK];
    __shared__ int bs[128];
    int t = threadIdx.x;
    if (t < 128) bs[t] = (t < NB) ? g_bsum[t] : 0;
    __syncthreads();
    // inclusive scan over 128 block sums (first 128 threads)
    for (int off = 1; off < 128; off <<= 1) {
        int tmp = 0;
        if (t < 128 && t >= off) tmp = bs[t - off];
        __syncthreads();
        if (t < 128) bs[t] += tmp;
        __syncthreads();
    }
    int base = (blockIdx.x == 0) ? 0 : bs[blockIdx.x - 1];

    int idx = blockIdx.x * SCAN_CHUNK + t;
    int v = (idx < N_NODES) ? g_cnt[idx] : 0;
    sh[t] = v;
    __syncthreads();
    for (int off = 1; off < SCAN_CHUNK; off <<= 1) {
        int tmp = (t >= off) ? sh[t - off] : 0;
        __syncthreads();
        sh[t] += tmp;
        __syncthreads();
    }
    if (idx < N_NODES) {
        int st = base + sh[t] - v;
        g_starts[idx] = st;
        g_cursor[idx] = st;
    }
}

// ---------------- CSR fill (cursor atomics; R13 known-good) ----------------
__global__ void k_fill(const int4* __restrict__ row4, const int4* __restrict__ col4,
                       const float4* __restrict__ wa4) {
    int i = blockIdx.x * blockDim.x + threadIdx.x;
    if (i >= N_EDGES / 4) return;
    int4   r = row4[i];
    int4   c = col4[i];
    float4 w = wa4[i];
    int p;
    p = atomicAdd(&g_cursor[c.x], 1); g_edges[p] = make_int2(r.x, __float_as_int(fabsf(w.x)));
    p = atomicAdd(&g_cursor[c.y], 1); g_edges[p] = make_int2(r.y, __float_as_int(fabsf(w.y)));
    p = atomicAdd(&g_cursor[c.z], 1); g_edges[p] = make_int2(r.z, __float_as_int(fabsf(w.z)));
    p = atomicAdd(&g_cursor[c.w], 1); g_edges[p] = make_int2(r.w, __float_as_int(fabsf(w.w)));
}

// ============ warp-MMA GEMM1 (m16n8k16 bf16): bufA = x @ W1 (raw fp32) =====
#define SA 216                      // bf16 row stride (conflict-free frags)
#define MM_B_OFF (128 * SA * 2)     // 55296
#define MM_SMEM  (MM_B_OFF + 64 * SA * 2)  // 82944

__global__ void __launch_bounds__(256) k_gemm1_mma(const float* __restrict__ x,
                                                   const float* __restrict__ W1) {
    extern __shared__ __align__(16) char smem[];
    __nv_bfloat16* As = (__nv_bfloat16*)smem;               // [128][SA]
    __nv_bfloat16* Bs = (__nv_bfloat16*)(smem + MM_B_OFF);  // [64][SA] = W1^T
    int tid = threadIdx.x;
    int m0  = blockIdx.x * 128;

    for (int i = tid; i < 128 * 4; i += 256) {
        int r = i >> 2, c = 200 + ((i & 3) << 1);
        *(u32*)(As + r * SA + c) = 0;
    }
    for (int i = tid; i < 64 * 4; i += 256) {
        int r = i >> 2, c = 200 + ((i & 3) << 1);
        *(u32*)(Bs + r * SA + c) = 0;
    }
    for (int f = tid; f < 128 * 50; f += 256) {
        int r = f / 50, c4 = f % 50;
        int mg = m0 + r;
        float4 v = make_float4(0.f, 0.f, 0.f, 0.f);
        if (mg < N_NODES) v = *(const float4*)(x + (size_t)mg * IN_CH + c4 * 4);
        u32 p0 = bf2_bits(__float22bfloat162_rn(make_float2(v.x, v.y)));
        u32 p1 = bf2_bits(__float22bfloat162_rn(make_float2(v.z, v.w)));
        *(uint2*)(As + r * SA + c4 * 4) = make_uint2(p0, p1);
    }
    for (int idx = tid; idx < IN_CH * HID; idx += 256) {
        int k = idx / HID, n = idx % HID;
        Bs[n * SA + k] = __float2bfloat16(W1[idx]);
    }
    __syncthreads();

    int warp = tid >> 5, lane = tid & 31;
    int grp = lane >> 2, t4 = lane & 3;
    const __nv_bfloat16* Ar0 = As + (warp * 16 + grp) * SA;
    const __nv_bfloat16* Ar1 = Ar0 + 8 * SA;

    float c[8][4];
#pragma unroll
    for (int nt = 0; nt < 8; nt++)
#pragma unroll
        for (int j = 0; j < 4; j++) c[nt][j] = 0.f;

#pragma unroll
    for (int s = 0; s < 13; s++) {
        int k0 = s * 16;
        u32 a0 = *(const u32*)(Ar0 + k0 + 2 * t4);
        u32 a1 = *(const u32*)(Ar1 + k0 + 2 * t4);
        u32 a2 = *(const u32*)(Ar0 + k0 + 2 * t4 + 8);
        u32 a3 = *(const u32*)(Ar1 + k0 + 2 * t4 + 8);
#pragma unroll
        for (int nt = 0; nt < 8; nt++) {
            const __nv_bfloat16* Bp = Bs + (nt * 8 + grp) * SA + k0 + 2 * t4;
            u32 b0 = *(const u32*)(Bp);
            u32 b1 = *(const u32*)(Bp + 8);
            asm volatile(
                "mma.sync.aligned.m16n8k16.row.col.f32.bf16.bf16.f32 "
                "{%0,%1,%2,%3}, {%4,%5,%6,%7}, {%8,%9}, {%0,%1,%2,%3};"
                : "+f"(c[nt][0]), "+f"(c[nt][1]), "+f"(c[nt][2]), "+f"(c[nt][3])
                : "r"(a0), "r"(a1), "r"(a2), "r"(a3), "r"(b0), "r"(b1));
        }
    }

    int mA = m0 + warp * 16 + grp;
    int mB = mA + 8;
#pragma unroll
    for (int nt = 0; nt < 8; nt++) {
        int col = nt * 8 + 2 * t4;
        if (mA < N_NODES)
            *(float2*)(g_bufA + (size_t)mA * 64 + col) = make_float2(c[nt][0], c[nt][1]);
        if (mB < N_NODES)
            *(float2*)(g_bufA + (size_t)mB * 64 + col) = make_float2(c[nt][2], c[nt][3]);
    }
}

// == 3xTF32 warp-MMA GEMM2 + pooling: pooled[batch[m]] += relu(t@W2+b2) =====
#define SB2 68                              // fp32 row stride; 68 % 32 == 4
#define P2_BH_OFF (128 * SB2 * 4)           // 34816
#define P2_BL_OFF (P2_BH_OFF + 64 * SB2 * 4)// 52224
#define P2_SMEM   (P2_BL_OFF + 64 * SB2 * 4)// 69632 (C overlays A tile)

__global__ void __launch_bounds__(256) k_gemm2pool_tf32(const float* __restrict__ W2,
                                                        const float* __restrict__ b2,
                                                        const int* __restrict__ batch) {
    extern __shared__ __align__(16) char smem[];
    float* As = (float*)smem;                 // [128][SB2] = t tile (fp32)
    u32*   Bh = (u32*)(smem + P2_BH_OFF);     // [64][SB2]  = tf32(W2^T)
    u32*   Bl = (u32*)(smem + P2_BL_OFF);     // [64][SB2]  = tf32(residual)
    int tid = threadIdx.x;
    int m0  = blockIdx.x * 128;

    for (int f = tid; f < 128 * 16; f += 256) {
        int r = f >> 4, q = f & 15;
        int mg = m0 + r;
        float4 v = make_float4(0.f, 0.f, 0.f, 0.f);
        if (mg < N_NODES) v = *(const float4*)(g_bufA + (size_t)mg * 64 + q * 4);
        *(float4*)(As + r * SB2 + q * 4) = v;
    }
    for (int idx = tid; idx < HID * HID; idx += 256) {
        int k = idx / HID, n = idx % HID;
        float w = W2[idx];
        u32 hb = tf32_hi_bits(w);
        float lo = w - __uint_as_float(hb);
        Bh[n * SB2 + k] = hb;
        Bl[n * SB2 + k] = tf32_hi_bits(lo);
    }
    __syncthreads();

    int warp = tid >> 5, lane = tid & 31;
    int grp = lane >> 2, t4 = lane & 3;
    int rA = warp * 16 + grp;
    const float* Ar0 = As + rA * SB2;
    const float* Ar1 = Ar0 + 8 * SB2;

    float c[8][4];
#pragma unroll
    for (int nt = 0; nt < 8; nt++)
#pragma unroll
        for (int j = 0; j < 4; j++) c[nt][j] = 0.f;

#pragma unroll
    for (int s = 0; s < 8; s++) {
        int k0 = s * 8;
        float av0 = Ar0[k0 + t4];
        float av1 = Ar1[k0 + t4];
        float av2 = Ar0[k0 + t4 + 4];
        float av3 = Ar1[k0 + t4 + 4];
        u32 ah0 = tf32_hi_bits(av0), ah1 = tf32_hi_bits(av1);
        u32 ah2 = tf32_hi_bits(av2), ah3 = tf32_hi_bits(av3);
        u32 al0 = tf32_hi_bits(av0 - __uint_as_float(ah0));
        u32 al1 = tf32_hi_bits(av1 - __uint_as_float(ah1));
        u32 al2 = tf32_hi_bits(av2 - __uint_as_float(ah2));
        u32 al3 = tf32_hi_bits(av3 - __uint_as_float(ah3));
#pragma unroll
        for (int nt = 0; nt < 8; nt++) {
            int boff = (nt * 8 + grp) * SB2 + k0;
            u32 bh0 = Bh[boff + t4], bh1 = Bh[boff + t4 + 4];
            u32 bl0 = Bl[boff + t4], bl1 = Bl[boff + t4 + 4];
            asm volatile(
                "mma.sync.aligned.m16n8k8.row.col.f32.tf32.tf32.f32 "
                "{%0,%1,%2,%3}, {%4,%5,%6,%7}, {%8,%9}, {%0,%1,%2,%3};"
                : "+f"(c[nt][0]), "+f"(c[nt][1]), "+f"(c[nt][2]), "+f"(c[nt][3])
                : "r"(ah0), "r"(ah1), "r"(ah2), "r"(ah3), "r"(bl0), "r"(bl1));
            asm volatile(
                "mma.sync.aligned.m16n8k8.row.col.f32.tf32.tf32.f32 "
                "{%0,%1,%2,%3}, {%4,%5,%6,%7}, {%8,%9}, {%0,%1,%2,%3};"
                : "+f"(c[nt][0]), "+f"(c[nt][1]), "+f"(c[nt][2]), "+f"(c[nt][3])
                : "r"(al0), "r"(al1), "r"(al2), "r"(al3), "r"(bh0), "r"(bh1));
            asm volatile(
                "mma.sync.aligned.m16n8k8.row.col.f32.tf32.tf32.f32 "
                "{%0,%1,%2,%3}, {%4,%5,%6,%7}, {%8,%9}, {%0,%1,%2,%3};"
                : "+f"(c[nt][0]), "+f"(c[nt][1]), "+f"(c[nt][2]), "+f"(c[nt][3])
                : "r"(ah0), "r"(ah1), "r"(ah2), "r"(ah3), "r"(bh0), "r"(bh1));
        }
    }
    __syncthreads();

    float* Cs = (float*)smem;
#pragma unroll
    for (int nt = 0; nt < 8; nt++) {
        int col = nt * 8 + 2 * t4;
        *(float2*)(Cs + rA * SB2 + col)       = make_float2(c[nt][0], c[nt][1]);
        *(float2*)(Cs + (rA + 8) * SB2 + col) = make_float2(c[nt][2], c[nt][3]);
    }
    __syncthreads();

    int r0 = (tid >> 4) * 8;
    int c0 = (tid & 15) * 4;
    float4 bv = *(const float4*)(b2 + c0);
#pragma unroll
    for (int i = 0; i < 8; i++) {
        int m = m0 + r0 + i;
        if (m < N_NODES) {
            float4 v = *(float4*)(Cs + (r0 + i) * SB2 + c0);
            v.x = fmaxf(v.x + bv.x, 0.f);
            v.y = fmaxf(v.y + bv.y, 0.f);
            v.z = fmaxf(v.z + bv.z, 0.f);
            v.w = fmaxf(v.w + bv.w, 0.f);
            int g = batch[m];
            float* dst = g_pooled + g * 64 + c0;
#if __CUDA_ARCH__ >= 900
            atomicAdd((float4*)dst, v);
#else
            atomicAdd(dst + 0, v.x);
            atomicAdd(dst + 1, v.y);
            atomicAdd(dst + 2, v.z);
            atomicAdd(dst + 3, v.w);
#endif
        }
    }
}

// ---------------- convert bufA -> bf16 with dinv scale ----------------
__global__ void k_conv() {
    int i = blockIdx.x * blockDim.x + threadIdx.x;   // one uint4 (8 feats) / thread
    if (i >= N_NODES * 8) return;
    int n = i >> 3;
    float d = g_deg[n];
    const float* src = g_bufA + (size_t)i * 8;
    float4 v0 = *(const float4*)(src);
    float4 v1 = *(const float4*)(src + 4);
    uint4 o;
    o.x = bf2_bits(__float22bfloat162_rn(make_float2(v0.x * d, v0.y * d)));
    o.y = bf2_bits(__float22bfloat162_rn(make_float2(v0.z * d, v0.w * d)));
    o.z = bf2_bits(__float22bfloat162_rn(make_float2(v1.x * d, v1.y * d)));
    o.w = bf2_bits(__float22bfloat162_rn(make_float2(v1.z * d, v1.w * d)));
    g_hbf[i] = o;
}

// ---- 4-edges-per-warp gather: 8 lanes/edge, 0.5 LDG per edge --------------
__device__ __forceinline__ void gather_core(const uint4* __restrict__ h,
                                            int s, int e, int eg, int fl,
                                            float acc[8]) {
#pragma unroll 2
    for (int i = s; i < e; i += 4) {
        int idx = i + eg;
        int cl  = idx < e ? idx : (e - 1);
        int2 ed = g_edges[cl];
        float w = idx < e ? __int_as_float(ed.y) : 0.f;
        uint4 hv = h[(size_t)ed.x * 8 + fl];
        float2 p0 = __bfloat1622float2(*(__nv_bfloat162*)&hv.x);
        float2 p1 = __bfloat1622float2(*(__nv_bfloat162*)&hv.y);
        float2 p2 = __bfloat1622float2(*(__nv_bfloat162*)&hv.z);
        float2 p3 = __bfloat1622float2(*(__nv_bfloat162*)&hv.w);
        acc[0] = fmaf(w, p0.x, acc[0]);
        acc[1] = fmaf(w, p0.y, acc[1]);
        acc[2] = fmaf(w, p1.x, acc[2]);
        acc[3] = fmaf(w, p1.y, acc[3]);
        acc[4] = fmaf(w, p2.x, acc[4]);
        acc[5] = fmaf(w, p2.y, acc[5]);
        acc[6] = fmaf(w, p3.x, acc[6]);
        acc[7] = fmaf(w, p3.y, acc[7]);
    }
#pragma unroll
    for (int k = 0; k < 8; k++) {
        acc[k] += __shfl_xor_sync(0xffffffffu, acc[k], 8);
        acc[k] += __shfl_xor_sync(0xffffffffu, acc[k], 16);
    }
}

// layer 1: g_hbf2[n] = bf16( dinv * relu( dinv*(sum + hn) + b1 ) )
__global__ void __launch_bounds__(256) k_gather1(const float* __restrict__ bias) {
    int wid  = (blockIdx.x * blockDim.x + threadIdx.x) >> 5;
    int lane = threadIdx.x & 31;
    if (wid >= N_NODES) return;
    int s = g_starts[wid];
    int e = g_starts[wid + 1];
    int eg = lane >> 3;
    int fl = lane & 7;
    float acc[8] = {0.f, 0.f, 0.f, 0.f, 0.f, 0.f, 0.f, 0.f};
    gather_core(g_hbf, s, e, eg, fl, acc);
    if (eg == 0) {
        uint4 hn = g_hbf[(size_t)wid * 8 + fl];
        float2 q0 = __bfloat1622float2(*(__nv_bfloat162*)&hn.x);
        float2 q1 = __bfloat1622float2(*(__nv_bfloat162*)&hn.y);
        float2 q2 = __bfloat1622float2(*(__nv_bfloat162*)&hn.z);
        float2 q3 = __bfloat1622float2(*(__nv_bfloat162*)&hn.w);
        float d = g_deg[wid];
        float4 bA = *(const float4*)(bias + fl * 8);
        float4 bB = *(const float4*)(bias + fl * 8 + 4);
        float o0 = fmaxf(fmaf(d, acc[0] + q0.x, bA.x), 0.f) * d;
        float o1 = fmaxf(fmaf(d, acc[1] + q0.y, bA.y), 0.f) * d;
        float o2 = fmaxf(fmaf(d, acc[2] + q1.x, bA.z), 0.f) * d;
        float o3 = fmaxf(fmaf(d, acc[3] + q1.y, bA.w), 0.f) * d;
        float o4 = fmaxf(fmaf(d, acc[4] + q2.x, bB.x), 0.f) * d;
        float o5 = fmaxf(fmaf(d, acc[5] + q2.y, bB.y), 0.f) * d;
        float o6 = fmaxf(fmaf(d, acc[6] + q3.x, bB.z), 0.f) * d;
        float o7 = fmaxf(fmaf(d, acc[7] + q3.y, bB.w), 0.f) * d;
        uint4 o;
        o.x = bf2_bits(__float22bfloat162_rn(make_float2(o0, o1)));
        o.y = bf2_bits(__float22bfloat162_rn(make_float2(o2, o3)));
        o.z = bf2_bits(__float22bfloat162_rn(make_float2(o4, o5)));
        o.w = bf2_bits(__float22bfloat162_rn(make_float2(o6, o7)));
        g_hbf2[(size_t)wid * 8 + fl] = o;
    }
}

// layer 2 aggregation: g_bufA[n,:] = dinv*(sum + hn)   (fp32 t)
__global__ void __launch_bounds__(256) k_gather2() {
    int wid  = (blockIdx.x * blockDim.x + threadIdx.x) >> 5;
    int lane = threadIdx.x & 31;
    if (wid >= N_NODES) return;
    int s = g_starts[wid];
    int e = g_starts[wid + 1];
    int eg = lane >> 3;
    int fl = lane & 7;
    float acc[8] = {0.f, 0.f, 0.f, 0.f, 0.f, 0.f, 0.f, 0.f};
    gather_core(g_hbf2, s, e, eg, fl, acc);
    if (eg == 0) {
        uint4 hn = g_hbf2[(size_t)wid * 8 + fl];
        float2 q0 = __bfloat1622float2(*(__nv_bfloat162*)&hn.x);
        float2 q1 = __bfloat1622float2(*(__nv_bfloat162*)&hn.y);
        float2 q2 = __bfloat1622float2(*(__nv_bfloat162*)&hn.z);
        float2 q3 = __bfloat1622float2(*(__nv_bfloat162*)&hn.w);
        float d = g_deg[wid];
        float* dst = g_bufA + (size_t)wid * 64 + fl * 8;
        float4 oA, oB;
        oA.x = d * (acc[0] + q0.x);
        oA.y = d * (acc[1] + q0.y);
        oA.z = d * (acc[2] + q1.x);
        oA.w = d * (acc[3] + q1.y);
        oB.x = d * (acc[4] + q2.x);
        oB.y = d * (acc[5] + q2.y);
        oB.z = d * (acc[6] + q3.x);
        oB.w = d * (acc[7] + q3.y);
        *(float4*)(dst)     = oA;
        *(float4*)(dst + 4) = oB;
    }
}

// ------- final MLP (graph counts via binary search on sorted batch) --------
__global__ void __launch_bounds__(256) k_mlp(const int* __restrict__ batch,
                                             const float* __restrict__ L1,
                                             const float* __restrict__ c1,
                                             const float* __restrict__ L2,
                                             const float* __restrict__ c2,
                                             float* __restrict__ out) {
    int g = blockIdx.x;
    __shared__ float pm[HID];
    __shared__ float fea[IN_CH];
    __shared__ float red[256];
    __shared__ int scnt;
    int tid = threadIdx.x;
    if (tid == 0) {
        // lower bound of g and of g+1 in sorted batch
        int lo = 0, hi = N_NODES;
        while (lo < hi) { int m = (lo + hi) >> 1; if (batch[m] < g) lo = m + 1; else hi = m; }
        int lo2 = lo, hi2 = N_NODES;
        while (lo2 < hi2) { int m = (lo2 + hi2) >> 1; if (batch[m] < g + 1) lo2 = m + 1; else hi2 = m; }
        scnt = lo2 - lo;
    }
    __syncthreads();
    if (tid < HID) {
        float cv = (float)scnt;
        pm[tid] = g_pooled[g * HID + tid] / fmaxf(cv, 1.0f);
    }
    __syncthreads();
    if (tid < IN_CH) {
        float s = c1[tid];
#pragma unroll
        for (int k = 0; k < HID; k++) s = fmaf(pm[k], L1[k * IN_CH + tid], s);
        fea[tid] = fmaxf(s, 0.f);
    }
    __syncthreads();
    float p0 = 0.f, p1 = 0.f;
    if (tid < IN_CH) {
        float fv = fea[tid];
        p0 = fv * L2[tid * OUT_CH];
        p1 = fv * L2[tid * OUT_CH + 1];
    }
    red[tid] = p0; __syncthreads();
    for (int off = 128; off > 0; off >>= 1) {
        if (tid < off) red[tid] += red[tid + off];
        __syncthreads();
    }
    float s0 = red[0];
    __syncthreads();
    red[tid] = p1; __syncthreads();
    for (int off = 128; off > 0; off >>= 1) {
        if (tid < off) red[tid] += red[tid + off];
        __syncthreads();
    }
    if (tid == 0) {
        out[g * OUT_CH]     = s0     + c2[0];
        out[g * OUT_CH + 1] = red[0] + c2[1];
    }
}

// ---------------- launch ----------------
extern "C" void kernel_launch(void* const* d_in, const int* in_sizes, int n_in,
                              void* d_out, int out_size) {
    const float* x         = (const float*)d_in[0];
    const int*   edge_idx  = (const int*)d_in[1];
    const float* edge_attr = (const float*)d_in[2];
    const int*   batch     = (const int*)d_in[3];
    const float* W1        = (const float*)d_in[4];
    const float* b1        = (const float*)d_in[5];
    const float* W2        = (const float*)d_in[6];
    const float* b2        = (const float*)d_in[7];
    const float* L1        = (const float*)d_in[8];
    const float* c1        = (const float*)d_in[9];
    const float* L2        = (const float*)d_in[10];
    const float* c2        = (const float*)d_in[11];
    float* out = (float*)d_out;

    const int* row = edge_idx;
    const int* col = edge_idx + N_EDGES;

    static cudaStream_t s2 = nullptr;
    static cudaEvent_t  evF = nullptr, evD = nullptr, evJ = nullptr;
    if (s2 == nullptr) {
        cudaStreamCreateWithFlags(&s2, cudaStreamNonBlocking);
        cudaEventCreateWithFlags(&evF, cudaEventDisableTiming);
        cudaEventCreateWithFlags(&evD, cudaEventDisableTiming);
        cudaEventCreateWithFlags(&evJ, cudaEventDisableTiming);
        cudaFuncSetAttribute(k_gemm1_mma, cudaFuncAttributeMaxDynamicSharedMemorySize,
                             MM_SMEM);
        cudaFuncSetAttribute(k_gemm2pool_tf32, cudaFuncAttributeMaxDynamicSharedMemorySize,
                             P2_SMEM);
    }

    const int TB = 256;
    int nodeBlocks   = (N_NODES + TB - 1) / TB;
    int edge4Blocks  = (N_EDGES / 4 + TB - 1) / TB;
    int gemmBlocks   = (N_NODES + 127) / 128;
    int gatherBlocks = (N_NODES * 32 + TB - 1) / TB;
    int convBlocks   = (N_NODES * 8 + TB - 1) / TB;

    // fork: MMA GEMM1 (raw) has no dependencies, starts at t=0
    cudaEventRecord(evF, 0);
    cudaStreamWaitEvent(s2, evF, 0);
    k_gemm1_mma<<<gemmBlocks, 256, MM_SMEM, s2>>>(x, W1);  // bufA = x @ W1 (raw)

    k_init<<<nodeBlocks, TB>>>();
    k_hist<<<edge4Blocks, TB>>>((const int4*)col, (const float4*)edge_attr);
    k_scan1<<<NB, SCAN_CHUNK>>>();                    // dinv + cnt + block sums
    cudaEventRecord(evD, 0);                          // dinv ready

    cudaStreamWaitEvent(s2, evD, 0);
    k_conv<<<convBlocks, TB, 0, s2>>>();              // g_hbf = bf16(dinv*bufA)
    cudaEventRecord(evJ, s2);

    k_scan3<<<NB, SCAN_CHUNK>>>();                    // starts + cursor
    k_fill<<<edge4Blocks, TB>>>((const int4*)row, (const int4*)col,
                                (const float4*)edge_attr);

    cudaStreamWaitEvent(0, evJ, 0);                   // join

    k_gather1<<<gatherBlocks, TB>>>(b1);              // g_hbf2 = dinv*relu1 (bf16)
    k_gather2<<<gatherBlocks, TB>>>();                // g_bufA = t (fp32)
    k_gemm2pool_tf32<<<gemmBlocks, 256, P2_SMEM>>>(W2, b2, batch);
    k_mlp<<<N_GRAPHS, 256>>>(batch, L1, c1, L2, c2, out);
}